// round 3
// baseline (speedup 1.0000x reference)
#include <cuda_runtime.h>

// ----------------------------------------------------------------------------
// TensorProductWithScalarComponents — fp32 baseline (Round 3 = R2 resubmit;
// R2 never ran: GB300 container infra failure)
//
//   out[n,w2,mc] = (1/(8m)) * sum_{u,v,w} Wl[w,w2] Wt[u,v,w] x[n,u,mc] y[n,v]
//
// Stage 1: fold weights once per launch: C[u,v,w2] = c * sum_w Wt[u,v,w]*Wl[w,w2]
// Stage 2: per block/mc, GEMM  Out[N x m] = F[N x m*64] @ C[m*64 x m],
//          F[n, u*64+v] = x[n,u,mc]*y[n,v] synthesized on the fly from SMEM tiles.
//
// Inputs are bound by ELEMENT COUNT (all 8 are distinct), removing the
// metadata-ordering assumption that produced the sqrt(2) uncorrelated output in R1.
// ----------------------------------------------------------------------------

#define NS        100000
#define TN        128     // samples per CTA tile
#define TNP       132     // padded row stride (floats) for sxT/syT
#define NTHREADS  256

// Folded weight scratch (L2-resident during main GEMMs)
__device__ float g_C0[128 * 64 * 128];  // 4 MB
__device__ float g_C1[64 * 64 * 64];    // 1 MB
__device__ float g_C2[32 * 64 * 32];    // 256 KB

// ---------------------------------------------------------------------------
// Stage 1: C[uv, w2] = c * sum_w Wt[uv, w] * Wl[w, w2]
// grid = m*64 blocks (one per (u,v)), block = m threads (one per w2)
// ---------------------------------------------------------------------------
template <int M, int BLK>
__global__ void precompute_kernel(const float* __restrict__ Wt,
                                  const float* __restrict__ Wl) {
    float* C = (BLK == 0) ? g_C0 : (BLK == 1) ? g_C1 : g_C2;
    __shared__ float wt[M];
    const int uv = blockIdx.x;
    const float* wtrow = Wt + (size_t)uv * M;
    for (int w = threadIdx.x; w < M; w += blockDim.x) wt[w] = wtrow[w];
    __syncthreads();

    const int w2 = threadIdx.x;
    float acc = 0.f;
#pragma unroll 4
    for (int w = 0; w < M; ++w) acc = fmaf(wt[w], Wl[w * M + w2], acc);
    C[(size_t)uv * M + w2] = acc * (1.0f / (8.0f * (float)M));
}

// ---------------------------------------------------------------------------
// Stage 2: one CTA computes a [TN samples x M outputs] tile for one mc.
// K = M*64 split as outer loop over u (M iters) x inner loop over v (64).
// C chunk for current u staged in SMEM; x,y tiles resident in SMEM (transposed,
// padded). Each thread owns an 8-sample x (M/16)-w2 register micro-tile.
// ---------------------------------------------------------------------------
template <int M, int D, int BLK, int XOFF>
__global__ __launch_bounds__(NTHREADS, 1)
void block_kernel(const float* __restrict__ x,
                  const float* __restrict__ y,
                  float* __restrict__ out) {
    const float* C = (BLK == 0) ? g_C0 : (BLK == 1) ? g_C1 : g_C2;
    constexpr int W2P = M / 16;  // w2 values per thread: 8 / 4 / 2

    extern __shared__ float sm[];
    float* sxT = sm;                    // [M][TNP]   x block col-major by sample
    float* syT = sm + M * TNP;          // [64][TNP]
    float* sc  = syT + 64 * TNP;        // [64][M]    C rows for current u

    const int tid = threadIdx.x;
    const int mc  = blockIdx.y;
    const int n0  = blockIdx.x * TN;
    int nrem = NS - n0;
    if (nrem > TN) nrem = TN;

    // Load x tile (this block, this mc), transposed into sxT[u][s]
    for (int idx = tid; idx < M * TN; idx += NTHREADS) {
        const int s = idx / M;
        const int u = idx - s * M;
        float v = 0.f;
        if (s < nrem) v = x[(size_t)(n0 + s) * 480 + XOFF + u * D + mc];
        sxT[u * TNP + s] = v;
    }
    // Load y tile transposed into syT[v][s]
    for (int idx = tid; idx < 64 * TN; idx += NTHREADS) {
        const int s = idx >> 6;
        const int vv = idx & 63;
        float v = 0.f;
        if (s < nrem) v = y[(size_t)(n0 + s) * 64 + vv];
        syT[vv * TNP + s] = v;
    }

    const int ts = tid >> 4;        // 0..15 sample group
    const int tw = tid & 15;        // 0..15 w2 group
    const int s0 = ts * 8;
    const int w0 = tw * W2P;

    float acc[8][W2P];
#pragma unroll
    for (int i = 0; i < 8; ++i)
#pragma unroll
        for (int j = 0; j < W2P; ++j) acc[i][j] = 0.f;

    for (int u = 0; u < M; ++u) {
        __syncthreads();  // protect sc from previous iter; 1st iter: x/y tiles
        {
            const float* Crow = C + (size_t)u * 64 * M;
            for (int idx = tid; idx < 64 * M; idx += NTHREADS) sc[idx] = Crow[idx];
        }
        __syncthreads();

        float4 xa = *(const float4*)(sxT + u * TNP + s0);
        float4 xb = *(const float4*)(sxT + u * TNP + s0 + 4);
        float xu[8] = {xa.x, xa.y, xa.z, xa.w, xb.x, xb.y, xb.z, xb.w};

#pragma unroll 4
        for (int v = 0; v < 64; ++v) {
            float4 ya = *(const float4*)(syT + v * TNP + s0);
            float4 yb = *(const float4*)(syT + v * TNP + s0 + 4);
            float a[8] = {xu[0] * ya.x, xu[1] * ya.y, xu[2] * ya.z, xu[3] * ya.w,
                          xu[4] * yb.x, xu[5] * yb.y, xu[6] * yb.z, xu[7] * yb.w};

            float cf[W2P];
            const float* crow = sc + v * M + w0;
            if constexpr (W2P == 8) {
                float4 c0 = *(const float4*)crow;
                float4 c1 = *(const float4*)(crow + 4);
                cf[0] = c0.x; cf[1] = c0.y; cf[2] = c0.z; cf[3] = c0.w;
                cf[4] = c1.x; cf[5] = c1.y; cf[6] = c1.z; cf[7] = c1.w;
            } else if constexpr (W2P == 4) {
                float4 c0 = *(const float4*)crow;
                cf[0] = c0.x; cf[1] = c0.y; cf[2] = c0.z; cf[3] = c0.w;
            } else {
                float2 c0 = *(const float2*)crow;
                cf[0] = c0.x; cf[1] = c0.y;
            }

#pragma unroll
            for (int i = 0; i < 8; ++i)
#pragma unroll
                for (int j = 0; j < W2P; ++j)
                    acc[i][j] = fmaf(a[i], cf[j], acc[i][j]);
        }
    }

    // Store: out[n, XOFF + w2*D + mc]
#pragma unroll
    for (int i = 0; i < 8; ++i) {
        const int s = s0 + i;
        if (s < nrem) {
            float* orow = out + (size_t)(n0 + s) * 480 + XOFF;
#pragma unroll
            for (int j = 0; j < W2P; ++j) orow[(w0 + j) * D + mc] = acc[i][j];
        }
    }
}

// ---------------------------------------------------------------------------

extern "C" void kernel_launch(void* const* d_in, const int* in_sizes, int n_in,
                              void* d_out, int out_size) {
    // Bind inputs by element count — robust to any metadata ordering.
    // x: 48,000,000   y: 6,400,000
    // W_tp0: 1,048,576  W_tp1: 262,144  W_tp2: 65,536
    // W_lin0: 16,384    W_lin1: 4,096   W_lin2: 1,024
    const float *x = 0, *y = 0, *Wt0 = 0, *Wt1 = 0, *Wt2 = 0,
                *Wl0 = 0, *Wl1 = 0, *Wl2 = 0;
    for (int i = 0; i < n_in; ++i) {
        const float* p = (const float*)d_in[i];
        switch (in_sizes[i]) {
            case 48000000: x   = p; break;
            case 6400000:  y   = p; break;
            case 1048576:  Wt0 = p; break;
            case 262144:   Wt1 = p; break;
            case 65536:    Wt2 = p; break;
            case 16384:    Wl0 = p; break;
            case 4096:     Wl1 = p; break;
            case 1024:     Wl2 = p; break;
            default: break;
        }
    }
    float* out = (float*)d_out;

    // Stage 1: fold weights (cheap, ~10us total)
    precompute_kernel<128, 0><<<128 * 64, 128>>>(Wt0, Wl0);
    precompute_kernel<64, 1><<<64 * 64, 64>>>(Wt1, Wl1);
    precompute_kernel<32, 2><<<32 * 64, 32>>>(Wt2, Wl2);

    const int ntiles = (NS + TN - 1) / TN;  // 782

    constexpr int SM0 = (128 * TNP + 64 * TNP + 64 * 128) * 4;  // 134144 B
    constexpr int SM1 = (64 * TNP + 64 * TNP + 64 * 64) * 4;    //  83968 B
    constexpr int SM2 = (32 * TNP + 64 * TNP + 64 * 32) * 4;    //  58880 B

    cudaFuncSetAttribute(block_kernel<128, 1, 0, 0>,
                         cudaFuncAttributeMaxDynamicSharedMemorySize, SM0);
    cudaFuncSetAttribute(block_kernel<64, 3, 1, 128>,
                         cudaFuncAttributeMaxDynamicSharedMemorySize, SM1);
    cudaFuncSetAttribute(block_kernel<32, 5, 2, 320>,
                         cudaFuncAttributeMaxDynamicSharedMemorySize, SM2);

    // Stage 2: three block GEMMs (blockIdx.y = mc component)
    block_kernel<128, 1, 0, 0><<<dim3(ntiles, 1), NTHREADS, SM0>>>(x, y, out);
    block_kernel<64, 3, 1, 128><<<dim3(ntiles, 3), NTHREADS, SM1>>>(x, y, out);
    block_kernel<32, 5, 2, 320><<<dim3(ntiles, 5), NTHREADS, SM2>>>(x, y, out);
}

// round 7
// speedup vs baseline: 8.2505x; 8.2505x over previous
#include <cuda_runtime.h>
#include <cuda_fp16.h>
#include <cstdint>

// ----------------------------------------------------------------------------
// TensorProductWithScalarComponents — mma.sync fp16 HMMA (Round 7)
// (tcgen05 unavailable: harness emits compute_103 PTX, 'a'-features rejected)
//
//   out[n,w2,mc] = sum_{u,v} C[u,v,w2] * x[n,u,mc] * y[n,v]
//   C folded in stage 1 (fp16) and stored PRE-PACKED in mma.m16n8k16
//   B-fragment order, so the hot loop reads B as one LDS.64 per fragment.
//   A fragments are synthesized in registers from y (preloaded per-thread in
//   fragment positions) and x (SMEM tile): 4 hmul2 per k-step. No ldmatrix.
// ----------------------------------------------------------------------------

#define NS       100000
#define TN       128      // samples per CTA (8 warps x 16)
#define NTHREADS 256
#define XS       130      // padded x-tile stride (halfs), conflict-free STS

// Folded weights, fp16, fragment-packed per 64-wide u-chunk
__device__ __half g_C0[128 * 64 * 128];  // 2 MB
__device__ __half g_C1[64 * 64 * 64];    // 512 KB
__device__ __half g_C2[32 * 64 * 32];    // 128 KB

__device__ __forceinline__ uint32_t hmul2u(uint32_t a, uint32_t b) {
    __half2 r = __hmul2(*(__half2*)&a, *(__half2*)&b);
    return *(uint32_t*)&r;
}

__device__ __forceinline__ void mma16816(float* c, uint32_t a0, uint32_t a1,
                                         uint32_t a2, uint32_t a3,
                                         uint32_t b0, uint32_t b1) {
    asm volatile(
        "mma.sync.aligned.m16n8k16.row.col.f32.f16.f16.f32 "
        "{%0,%1,%2,%3},{%4,%5,%6,%7},{%8,%9},{%0,%1,%2,%3};"
        : "+f"(c[0]), "+f"(c[1]), "+f"(c[2]), "+f"(c[3])
        : "r"(a0), "r"(a1), "r"(a2), "r"(a3), "r"(b0), "r"(b1));
}

// ---------------------------------------------------------------------------
// Stage 1: C[u,v,w2] = (1/(8m)) * sum_w Wt[uv,w]*Wl[w,w2], written fp16 into
// mma B-fragment order within each u-chunk:
//   kstep=v/16, kr=v%16, ntile=w2/8, cc=w2%8
//   lane = cc*4 + (kr%8)/2 ; slot = (kr&1) + 2*(kr/8)
//   half index = u*64*M + ((kstep*(M/8)+ntile)*32 + lane)*4 + slot
// ---------------------------------------------------------------------------
template <int M, int BLK>
__global__ void precompute_kernel(const float* __restrict__ Wt,
                                  const float* __restrict__ Wl) {
    __half* C = (BLK == 0) ? g_C0 : (BLK == 1) ? g_C1 : g_C2;
    __shared__ float wt[M];
    const int uv = blockIdx.x;
    const float* wtrow = Wt + (size_t)uv * M;
    for (int w = threadIdx.x; w < M; w += blockDim.x) wt[w] = wtrow[w];
    __syncthreads();

    const int w2 = threadIdx.x;
    float acc = 0.f;
#pragma unroll 4
    for (int w = 0; w < M; ++w) acc = fmaf(wt[w], Wl[w * M + w2], acc);
    acc *= (1.0f / (8.0f * (float)M));

    const int u = uv >> 6, v = uv & 63;
    const uint32_t lane = (uint32_t)(w2 & 7) * 4 + ((v & 7) >> 1);
    const uint32_t slot = (uint32_t)(v & 1) + (((v >> 3) & 1) << 1);
    const uint32_t idx = (uint32_t)u * (64u * M) +
                         (((uint32_t)(v >> 4) * (M / 8) + (w2 >> 3)) * 32u + lane) * 4u + slot;
    C[idx] = __float2half(acc);
}

// ---------------------------------------------------------------------------
// Stage 2: HMMA GEMM. CTA = 128 samples x M outputs, one mc.
// K = M*64, streamed in 64-wide u-chunks (4 k16-steps each).
// ---------------------------------------------------------------------------
template <int M, int D, int BLK, int XOFF>
__global__ __launch_bounds__(NTHREADS)
void mma_kernel(const float* __restrict__ x,
                const float* __restrict__ y,
                float* __restrict__ out) {
    constexpr int NT = M / 8;       // n-tiles per warp row
    constexpr int U  = M;           // u-chunks
    constexpr int CH = 64 * M;      // halfs per B chunk
    constexpr int CPT = CH / 8 / NTHREADS;  // uint4 copies per thread (>=1)

    const __half* Cg = (BLK == 0) ? g_C0 : (BLK == 1) ? g_C1 : g_C2;

    extern __shared__ char smem[];
    __half* sx = (__half*)smem;                 // [M][XS] x tile (fp16, transposed)
    __half* Bs = (__half*)(smem + M * XS * 2);  // [2][CH] double-buffered B chunks

    const int tid  = threadIdx.x;
    const int wid  = tid >> 5;
    const int lane = tid & 31;
    const int mc   = blockIdx.y;
    const int n0   = blockIdx.x * TN;
    int nrem = NS - n0; if (nrem > TN) nrem = TN;

    const int s1 = wid * 16 + (lane >> 2);  // this thread's two sample rows
    const int s2 = s1 + 8;

    // ---- preload y in A-fragment positions (fp16 pairs); same for all u ----
    // slot g=2k:   v = 16k + 2*(lane%4)   -> halves {v, v+1}
    // slot g=2k+1: v = 16k + 2*(lane%4)+8 -> halves {v+8, v+9}
    uint32_t yv[2][8];
#pragma unroll
    for (int i = 0; i < 2; ++i) {
        const int s = (i == 0) ? s1 : s2;
        const bool valid = s < nrem;
        const float* yr = y + (size_t)(n0 + s) * 64;
#pragma unroll
        for (int k = 0; k < 4; ++k) {
            const int v0 = 16 * k + 2 * (lane & 3);
            float2 p = make_float2(0.f, 0.f), q = make_float2(0.f, 0.f);
            if (valid) {
                p = *(const float2*)(yr + v0);
                q = *(const float2*)(yr + v0 + 8);
            }
            __half2 hp = __floats2half2_rn(p.x, p.y);
            __half2 hq = __floats2half2_rn(q.x, q.y);
            yv[i][2 * k]     = *(uint32_t*)&hp;
            yv[i][2 * k + 1] = *(uint32_t*)&hq;
        }
    }

    // ---- x tile -> SMEM fp16, transposed [u][s] ----
    for (int idx = tid; idx < M * TN; idx += NTHREADS) {
        const int u = idx % M;        // consecutive threads -> consecutive u (coalesced, D=1)
        const int s = idx / M;
        float v = 0.f;
        if (s < nrem) v = x[(size_t)(n0 + s) * 480 + XOFF + u * D + mc];
        sx[u * XS + s] = __float2half(v);
    }

    float acc[NT][4];
#pragma unroll
    for (int t = 0; t < NT; ++t)
#pragma unroll
        for (int j = 0; j < 4; ++j) acc[t][j] = 0.f;

    // ---- main loop over u-chunks ----
    for (int u = 0; u < U; ++u) {
        // stage B chunk (fragment-packed) into Bs[u&1]
        {
            const uint4* src = (const uint4*)(Cg + (size_t)u * CH);
            uint4* dst = (uint4*)(Bs + (u & 1) * CH);
#pragma unroll
            for (int i = 0; i < CPT; ++i)
                dst[tid + i * NTHREADS] = src[tid + i * NTHREADS];
        }
        __syncthreads();  // also covers sx on first iteration; protects buf reuse (u-2)

        const __half xh1 = sx[u * XS + s1];
        const __half xh2 = sx[u * XS + s2];
        __half2 x1h = __half2half2(xh1);
        __half2 x2h = __half2half2(xh2);
        const uint32_t x1p = *(uint32_t*)&x1h;
        const uint32_t x2p = *(uint32_t*)&x2h;

        const uint2* bp = (const uint2*)(Bs + (u & 1) * CH) + lane;

#pragma unroll
        for (int k = 0; k < 4; ++k) {
            const uint32_t a0 = hmul2u(yv[0][2 * k],     x1p);
            const uint32_t a1 = hmul2u(yv[1][2 * k],     x2p);
            const uint32_t a2 = hmul2u(yv[0][2 * k + 1], x1p);
            const uint32_t a3 = hmul2u(yv[1][2 * k + 1], x2p);
#pragma unroll
            for (int nt = 0; nt < NT; ++nt) {
                const uint2 b = bp[(k * NT + nt) * 32];
                mma16816(acc[nt], a0, a1, a2, a3, b.x, b.y);
            }
        }
    }

    // ---- store: c0,c1 -> row s1 cols 2*(lane%4)+{0,1}; c2,c3 -> row s2 ----
    const int c0 = 2 * (lane & 3);
    if (s1 < nrem) {
        float* orow = out + (size_t)(n0 + s1) * 480 + XOFF + mc;
#pragma unroll
        for (int nt = 0; nt < NT; ++nt) {
            const int w2 = nt * 8 + c0;
            orow[(size_t)w2 * D]       = acc[nt][0];
            orow[(size_t)(w2 + 1) * D] = acc[nt][1];
        }
    }
    if (s2 < nrem) {
        float* orow = out + (size_t)(n0 + s2) * 480 + XOFF + mc;
#pragma unroll
        for (int nt = 0; nt < NT; ++nt) {
            const int w2 = nt * 8 + c0;
            orow[(size_t)w2 * D]       = acc[nt][2];
            orow[(size_t)(w2 + 1) * D] = acc[nt][3];
        }
    }
}

// ---------------------------------------------------------------------------

extern "C" void kernel_launch(void* const* d_in, const int* in_sizes, int n_in,
                              void* d_out, int out_size) {
    // Bind inputs by element count — robust to any metadata ordering.
    const float *x = 0, *y = 0, *Wt0 = 0, *Wt1 = 0, *Wt2 = 0,
                *Wl0 = 0, *Wl1 = 0, *Wl2 = 0;
    for (int i = 0; i < n_in; ++i) {
        const float* p = (const float*)d_in[i];
        switch (in_sizes[i]) {
            case 48000000: x   = p; break;
            case 6400000:  y   = p; break;
            case 1048576:  Wt0 = p; break;
            case 262144:   Wt1 = p; break;
            case 65536:    Wt2 = p; break;
            case 16384:    Wl0 = p; break;
            case 4096:     Wl1 = p; break;
            case 1024:     Wl2 = p; break;
            default: break;
        }
    }
    float* out = (float*)d_out;

    precompute_kernel<128, 0><<<128 * 64, 128>>>(Wt0, Wl0);
    precompute_kernel<64, 1><<<64 * 64, 64>>>(Wt1, Wl1);
    precompute_kernel<32, 2><<<32 * 64, 32>>>(Wt2, Wl2);

    const int ntiles = (NS + TN - 1) / TN;  // 782

    constexpr int SM0 = (128 * XS + 2 * 64 * 128) * 2;  // 66048 B
    constexpr int SM1 = (64 * XS + 2 * 64 * 64) * 2;    // 33024 B
    constexpr int SM2 = (32 * XS + 2 * 64 * 32) * 2;    // 16512 B

    cudaFuncSetAttribute(mma_kernel<128, 1, 0, 0>,
                         cudaFuncAttributeMaxDynamicSharedMemorySize, SM0);
    cudaFuncSetAttribute(mma_kernel<64, 3, 1, 128>,
                         cudaFuncAttributeMaxDynamicSharedMemorySize, SM1);
    cudaFuncSetAttribute(mma_kernel<32, 5, 2, 320>,
                         cudaFuncAttributeMaxDynamicSharedMemorySize, SM2);

    mma_kernel<128, 1, 0, 0><<<dim3(ntiles, 1), NTHREADS, SM0>>>(x, y, out);
    mma_kernel<64, 3, 1, 128><<<dim3(ntiles, 3), NTHREADS, SM1>>>(x, y, out);
    mma_kernel<32, 5, 2, 320><<<dim3(ntiles, 5), NTHREADS, SM2>>>(x, y, out);
}